// round 3
// baseline (speedup 1.0000x reference)
#include <cuda_runtime.h>
#include <math.h>
#include <stdint.h>

#define BATCH 4
#define SEQ   1024
#define DM    1024
#define NH    16
#define HD    64
#define BH    (BATCH*NH)

// Scratch (device globals: allocation-free per harness rules)
__device__ float g_Qh [BATCH*NH*SEQ*HD];        // [B,H,S,hd]  (tf32-rounded)
__device__ float g_Kh [BATCH*NH*SEQ*HD];        // [B,H,S,hd]  (tf32-rounded)
__device__ float g_VhT[BATCH*NH*HD*SEQ];        // [B,H,hd,S]  (tf32-rounded)
__device__ float g_AO [BATCH*SEQ*DM];           // [B,S,D] attn out (fp32)
__device__ float g_PE [SEQ*HD];                 // sinusoidal PE table

// ---------------------------------------------------------------------------
__global__ void pe_init_kernel() {
    int idx = blockIdx.x * blockDim.x + threadIdx.x;
    if (idx >= SEQ * HD) return;
    int s = idx >> 6;
    int d = idx & 63;
    int de = d & ~1;
    float div = expf(-(float)de * 0.14391156831212787f);   // ln(10000)/64
    float ang = (float)s * div;
    g_PE[idx] = (d & 1) ? cosf(ang) : sinf(ang);
}

// ---------------------------------------------------------------------------
__device__ __forceinline__ uint32_t f2tf32(float x) {
    uint32_t r;
    asm("cvt.rna.tf32.f32 %0, %1;" : "=r"(r) : "f"(x));
    return r;
}
__device__ __forceinline__ float tfr(float x) { return __uint_as_float(f2tf32(x)); }

__device__ __forceinline__ void mma8(float* c, const uint32_t* a, const uint32_t* b) {
    asm volatile(
        "mma.sync.aligned.m16n8k8.row.col.f32.tf32.tf32.f32 "
        "{%0,%1,%2,%3},{%4,%5,%6,%7},{%8,%9},{%0,%1,%2,%3};"
        : "+f"(c[0]), "+f"(c[1]), "+f"(c[2]), "+f"(c[3])
        : "r"(a[0]), "r"(a[1]), "r"(a[2]), "r"(a[3]), "r"(b[0]), "r"(b[1]));
}

// ---------------------------------------------------------------------------
// Epilogue dispatch (projection / output GEMMs)
//   EPI 0: Q proj -> g_Qh  (+bias +PE, permute, tf32 round)
//   EPI 1: K proj -> g_Kh  (+bias +PE, permute, tf32 round)
//   EPI 2: V proj -> g_VhT (+bias, permute transposed, tf32 round)
//   EPI 5: O proj -> out   (+bias, fp32)
// ---------------------------------------------------------------------------
template<int EPI>
__device__ __forceinline__ void store_elem(int m, int n, float v,
                                           float* __restrict__ Cex,
                                           const float* __restrict__ bias) {
    if constexpr (EPI == 0 || EPI == 1) {
        int b = m >> 10, s = m & 1023, h = n >> 6, d = n & 63;
        v = tfr(v + bias[n] + g_PE[(s << 6) + d]);
        float* dst = (EPI == 0) ? g_Qh : g_Kh;
        dst[((size_t)((b * NH + h) * SEQ + s)) * HD + d] = v;
    } else if constexpr (EPI == 2) {
        int b = m >> 10, s = m & 1023, h = n >> 6, d = n & 63;
        v = tfr(v + bias[n]);
        g_VhT[((size_t)((b * NH + h) * HD + d)) * SEQ + s] = v;
    } else {
        v += bias[n];
        Cex[(size_t)m * DM + n] = v;
    }
}

// ---------------------------------------------------------------------------
// NT GEMM: C[M,N] = A[M,K] @ B[N,K]^T, K=1024.
// CTA 128x64, KC=16, 256 thr, warps 4(m)x2(n), warp 32x32.
// Shared memory holds mma FRAGMENTS (vector LDS.128 / LDS.64 in compute).
//   As groups: (tm 0..7, kk 0..1) -> 32 lanes x 4 floats
//   Bs groups: (tn 0..7, kk 0..1) -> 32 lanes x 2 floats
// ---------------------------------------------------------------------------
#define BM 128
#define BN 64
#define KC 16

__device__ __forceinline__ void stageA(float* as_, int r, int acol, float4 v) {
    int tm = r >> 4, rm = r & 15, gid = rm & 7;
    int e  = (rm >> 3) + ((acol & 4) ? 2 : 0);
    int kk = acol >> 3;
    float* p = as_ + (tm * 2 + kk) * 128 + gid * 16 + e;   // + j*4 per elem
    p[0]  = tfr(v.x);
    p[4]  = tfr(v.y);
    p[8]  = tfr(v.z);
    p[12] = tfr(v.w);
}
__device__ __forceinline__ void stageB(float* bs_, int n, int acol, float4 v) {
    int tn = n >> 3, gid = n & 7;
    int e  = (acol & 4) ? 1 : 0;
    int kk = acol >> 3;
    float* p = bs_ + (tn * 2 + kk) * 64 + gid * 8 + e;     // + j*2 per elem
    p[0] = tfr(v.x);
    p[2] = tfr(v.y);
    p[4] = tfr(v.z);
    p[6] = tfr(v.w);
}

template<int EPI>
__global__ __launch_bounds__(256)
void gemm_kernel(const float* __restrict__ Aex, const float* __restrict__ Bex,
                 float* __restrict__ Cex, const float* __restrict__ bias) {
    constexpr int K  = 1024;
    constexpr int KT = K / KC;

    const float* A = (EPI == 5) ? g_AO : Aex;
    const float* B = Bex;

    __shared__ float As[2][2048];
    __shared__ float Bs[2][1024];

    const int tid = threadIdx.x;
    const int cm = blockIdx.x * BM;
    const int cn = blockIdx.y * BN;

    const int arow = tid >> 2;          // 0..63
    const int acol = (tid & 3) * 4;     // 0,4,8,12
    const float* Aptr0 = A + (size_t)(cm + arow)      * K + acol;
    const float* Aptr1 = A + (size_t)(cm + arow + 64) * K + acol;
    const float* Bptr  = B + (size_t)(cn + arow)      * K + acol;

    const int wid  = tid >> 5;
    const int lane = tid & 31;
    const int gid  = lane >> 2;
    const int tg   = lane & 3;
    const int tmBase = (wid & 3) * 2;   // A m16-tile base
    const int tnBase = (wid >> 2) * 4;  // B n8-tile base
    const int wm = (wid & 3) * 32;
    const int wn = (wid >> 2) * 32;

    float acc[2][4][4];
#pragma unroll
    for (int i = 0; i < 2; i++)
#pragma unroll
        for (int j = 0; j < 4; j++)
#pragma unroll
            for (int l = 0; l < 4; l++) acc[i][j][l] = 0.f;

    // Prologue
    {
        float4 a0 = *(const float4*)(Aptr0);
        float4 a1 = *(const float4*)(Aptr1);
        float4 b0 = *(const float4*)(Bptr);
        stageA(As[0], arow,      acol, a0);
        stageA(As[0], arow + 64, acol, a1);
        stageB(Bs[0], arow,      acol, b0);
    }
    __syncthreads();

    for (int kt = 0; kt < KT; kt++) {
        const int buf = kt & 1;
        float4 ra0, ra1, rb0;
        const bool pf = (kt + 1 < KT);
        if (pf) {
            ra0 = *(const float4*)(Aptr0 + (kt + 1) * KC);
            ra1 = *(const float4*)(Aptr1 + (kt + 1) * KC);
            rb0 = *(const float4*)(Bptr  + (kt + 1) * KC);
        }

        const float* as_ = As[buf];
        const float* bs_ = Bs[buf];
#pragma unroll
        for (int kk = 0; kk < 2; kk++) {
            uint4 af[2];
            uint2 bf[4];
#pragma unroll
            for (int im = 0; im < 2; im++)
                af[im] = *(const uint4*)(as_ + ((tmBase + im) * 2 + kk) * 128 + lane * 4);
#pragma unroll
            for (int in_ = 0; in_ < 4; in_++)
                bf[in_] = *(const uint2*)(bs_ + ((tnBase + in_) * 2 + kk) * 64 + lane * 2);
#pragma unroll
            for (int im = 0; im < 2; im++)
#pragma unroll
                for (int in_ = 0; in_ < 4; in_++)
                    mma8(acc[im][in_], (const uint32_t*)&af[im], (const uint32_t*)&bf[in_]);
        }

        if (pf) {
            float* asn = As[buf ^ 1];
            float* bsn = Bs[buf ^ 1];
            stageA(asn, arow,      acol, ra0);
            stageA(asn, arow + 64, acol, ra1);
            stageB(bsn, arow,      acol, rb0);
        }
        __syncthreads();
    }

    // Epilogue
#pragma unroll
    for (int im = 0; im < 2; im++) {
#pragma unroll
        for (int in_ = 0; in_ < 4; in_++) {
            int r0 = cm + wm + im * 16 + gid;
            int c0 = cn + wn + in_ * 8 + tg * 2;
            store_elem<EPI>(r0,     c0,     acc[im][in_][0], Cex, bias);
            store_elem<EPI>(r0,     c0 + 1, acc[im][in_][1], Cex, bias);
            store_elem<EPI>(r0 + 8, c0,     acc[im][in_][2], Cex, bias);
            store_elem<EPI>(r0 + 8, c0 + 1, acc[im][in_][3], Cex, bias);
        }
    }
}

// ---------------------------------------------------------------------------
// Flash attention: one block per (q-tile of 128 rows, bh). 256 threads.
// Warp w owns q rows [w*16, w*16+16). Online softmax. K/V double-buffered.
// Q/K/V are already tf32-rounded, so raw bits feed mma exactly.
// Dynamic smem (floats): Ks[2][4096] | Vs[2][4096] | Ps[8][16*66]
// ---------------------------------------------------------------------------
#define FLASH_SMEM_FLOATS (16384 + 8448)
#define FLASH_SMEM_BYTES  (FLASH_SMEM_FLOATS * 4)

__device__ __forceinline__ void stageKV(float* dst, const float4* v, int ltn, int lgid, int cb) {
#pragma unroll
    for (int i = 0; i < 4; i++) {
        int c = cb + i * 4;
        int kk = c >> 3, e = (c & 4) ? 1 : 0;
        float* p = dst + (ltn * 8 + kk) * 64 + lgid * 8 + e;
        p[0] = v[i].x;
        p[2] = v[i].y;
        p[4] = v[i].z;
        p[6] = v[i].w;
    }
}

__global__ __launch_bounds__(256)
void flash_kernel() {
    extern __shared__ float sm[];
    float* KsB = sm;                // 2 x 4096
    float* VsB = sm + 8192;         // 2 x 4096
    float* Ps  = sm + 16384;        // 8 x 1056

    const int tid  = threadIdx.x;
    const int lane = tid & 31;
    const int w    = tid >> 5;
    const int gid  = lane >> 2;
    const int tg   = lane & 3;
    const int qt   = blockIdx.x;
    const int bh   = blockIdx.y;

    const float* Qb = g_Qh  + (size_t)bh * (SEQ * HD);
    const float* Kb = g_Kh  + (size_t)bh * (SEQ * HD);
    const float* Vb = g_VhT + (size_t)bh * (HD * SEQ);

    // Q fragments (registers, whole hd=64)
    uint32_t qf[8][4];
    {
        const float* q0 = Qb + (size_t)(qt * 128 + w * 16 + gid) * HD;
        const float* q1 = q0 + 8 * HD;
#pragma unroll
        for (int kk = 0; kk < 8; kk++) {
            qf[kk][0] = __float_as_uint(q0[kk * 8 + tg]);
            qf[kk][1] = __float_as_uint(q1[kk * 8 + tg]);
            qf[kk][2] = __float_as_uint(q0[kk * 8 + tg + 4]);
            qf[kk][3] = __float_as_uint(q1[kk * 8 + tg + 4]);
        }
    }

    // K/V tile loader indices
    const int ln   = tid >> 2;        // 0..63
    const int cb   = (tid & 3) * 16;  // col base
    const int lgid = ln & 7;
    const int ltn  = ln >> 3;

    float4 kb[4], vb[4];
#pragma unroll
    for (int i = 0; i < 4; i++) {
        kb[i] = *(const float4*)(Kb + (size_t)ln * HD + cb + i * 4);
        vb[i] = *(const float4*)(Vb + (size_t)ln * SEQ + cb + i * 4);
    }
    stageKV(KsB, kb, ltn, lgid, cb);
    stageKV(VsB, vb, ltn, lgid, cb);
    __syncthreads();

    float m0 = -1e30f, m1 = -1e30f, l0 = 0.f, l1 = 0.f;
    float ao[8][4];
#pragma unroll
    for (int t = 0; t < 8; t++)
#pragma unroll
        for (int j = 0; j < 4; j++) ao[t][j] = 0.f;

    float* Pw = Ps + w * 1056;

    for (int kt = 0; kt < 16; kt++) {
        const int buf = kt & 1;
        const float* ks = KsB + buf * 4096;
        const float* vs = VsB + buf * 4096;

        if (kt < 15) {
            const float* Kg = Kb + (size_t)(kt + 1) * 64 * HD;
            const float* Vg = Vb + (kt + 1) * 64;
#pragma unroll
            for (int i = 0; i < 4; i++) {
                kb[i] = *(const float4*)(Kg + (size_t)ln * HD + cb + i * 4);
                vb[i] = *(const float4*)(Vg + (size_t)ln * SEQ + cb + i * 4);
            }
        }

        // S tile = Q @ K^T (warp rows 16 x 64 keys)
        float s[8][4];
#pragma unroll
        for (int t = 0; t < 8; t++)
#pragma unroll
            for (int j = 0; j < 4; j++) s[t][j] = 0.f;

#pragma unroll
        for (int kk = 0; kk < 8; kk++) {
#pragma unroll
            for (int tn = 0; tn < 8; tn++) {
                uint2 bf = *(const uint2*)(ks + (tn * 8 + kk) * 64 + lane * 2);
                mma8(s[tn], qf[kk], (const uint32_t*)&bf);
            }
        }

        // scale + row max
        float t0 = -1e30f, t1 = -1e30f;
#pragma unroll
        for (int tn = 0; tn < 8; tn++) {
            s[tn][0] *= 0.125f; s[tn][1] *= 0.125f;
            s[tn][2] *= 0.125f; s[tn][3] *= 0.125f;
            t0 = fmaxf(t0, fmaxf(s[tn][0], s[tn][1]));
            t1 = fmaxf(t1, fmaxf(s[tn][2], s[tn][3]));
        }
        t0 = fmaxf(t0, __shfl_xor_sync(0xffffffffu, t0, 1));
        t0 = fmaxf(t0, __shfl_xor_sync(0xffffffffu, t0, 2));
        t1 = fmaxf(t1, __shfl_xor_sync(0xffffffffu, t1, 1));
        t1 = fmaxf(t1, __shfl_xor_sync(0xffffffffu, t1, 2));

        float mn0 = fmaxf(m0, t0), mn1 = fmaxf(m1, t1);
        float a0 = __expf(m0 - mn0), a1 = __expf(m1 - mn1);

        __syncwarp();   // prior P reads done before overwrite
        float rs0 = 0.f, rs1 = 0.f;
#pragma unroll
        for (int tn = 0; tn < 8; tn++) {
            float p0 = __expf(s[tn][0] - mn0);
            float p1 = __expf(s[tn][1] - mn0);
            float p2 = __expf(s[tn][2] - mn1);
            float p3 = __expf(s[tn][3] - mn1);
            rs0 += p0 + p1;
            rs1 += p2 + p3;
            float2 v01 = make_float2(tfr(p0), tfr(p1));
            float2 v23 = make_float2(tfr(p2), tfr(p3));
            *(float2*)(Pw + gid * 66 + tn * 8 + tg * 2)       = v01;
            *(float2*)(Pw + (gid + 8) * 66 + tn * 8 + tg * 2) = v23;
        }
        rs0 += __shfl_xor_sync(0xffffffffu, rs0, 1);
        rs0 += __shfl_xor_sync(0xffffffffu, rs0, 2);
        rs1 += __shfl_xor_sync(0xffffffffu, rs1, 1);
        rs1 += __shfl_xor_sync(0xffffffffu, rs1, 2);

        l0 = l0 * a0 + rs0;
        l1 = l1 * a1 + rs1;
        m0 = mn0; m1 = mn1;
#pragma unroll
        for (int tn = 0; tn < 8; tn++) {
            ao[tn][0] *= a0; ao[tn][1] *= a0;
            ao[tn][2] *= a1; ao[tn][3] *= a1;
        }
        __syncwarp();   // P visible to all lanes of this warp

        // O += P @ V
#pragma unroll
        for (int kc = 0; kc < 8; kc++) {
            uint32_t pa[4];
            pa[0] = __float_as_uint(Pw[gid * 66 + kc * 8 + tg]);
            pa[1] = __float_as_uint(Pw[(gid + 8) * 66 + kc * 8 + tg]);
            pa[2] = __float_as_uint(Pw[gid * 66 + kc * 8 + tg + 4]);
            pa[3] = __float_as_uint(Pw[(gid + 8) * 66 + kc * 8 + tg + 4]);
#pragma unroll
            for (int tn = 0; tn < 8; tn++) {
                uint2 bf = *(const uint2*)(vs + (tn * 8 + kc) * 64 + lane * 2);
                mma8(ao[tn], pa, (const uint32_t*)&bf);
            }
        }

        if (kt < 15) {
            stageKV(KsB + (buf ^ 1) * 4096, kb, ltn, lgid, cb);
            stageKV(VsB + (buf ^ 1) * 4096, vb, ltn, lgid, cb);
        }
        __syncthreads();
    }

    // normalize + store to g_AO [B,S,D]
    float i0 = 1.f / l0, i1 = 1.f / l1;
    int b = bh >> 4, h = bh & 15;
    size_t srow = (size_t)qt * 128 + w * 16 + gid;
    float* O0 = g_AO + ((size_t)b * SEQ + srow) * DM + h * HD + tg * 2;
    float* O1 = O0 + (size_t)8 * DM;
#pragma unroll
    for (int tn = 0; tn < 8; tn++) {
        *(float2*)(O0 + tn * 8) = make_float2(ao[tn][0] * i0, ao[tn][1] * i0);
        *(float2*)(O1 + tn * 8) = make_float2(ao[tn][2] * i1, ao[tn][3] * i1);
    }
}

// ---------------------------------------------------------------------------
extern "C" void kernel_launch(void* const* d_in, const int* in_sizes, int n_in,
                              void* d_out, int out_size) {
    const float* q  = (const float*)d_in[0];
    const float* k  = (const float*)d_in[1];
    const float* v  = (const float*)d_in[2];
    const float* Wq = (const float*)d_in[3];
    const float* bq = (const float*)d_in[4];
    const float* Wk = (const float*)d_in[5];
    const float* bk = (const float*)d_in[6];
    const float* Wv = (const float*)d_in[7];
    const float* bv = (const float*)d_in[8];
    const float* Wo = (const float*)d_in[9];
    const float* bo = (const float*)d_in[10];
    float* out = (float*)d_out;

    cudaFuncSetAttribute(flash_kernel, cudaFuncAttributeMaxDynamicSharedMemorySize,
                         FLASH_SMEM_BYTES);

    pe_init_kernel<<<256, 256>>>();

    gemm_kernel<0><<<dim3(32, 16), 256>>>(q, Wq, nullptr, bq);
    gemm_kernel<1><<<dim3(32, 16), 256>>>(k, Wk, nullptr, bk);
    gemm_kernel<2><<<dim3(32, 16), 256>>>(v, Wv, nullptr, bv);
    flash_kernel<<<dim3(8, 64), 256, FLASH_SMEM_BYTES>>>();
    gemm_kernel<5><<<dim3(32, 16), 256>>>(nullptr, Wo, out, bo);
}

// round 4
// speedup vs baseline: 1.6153x; 1.6153x over previous
#include <cuda_runtime.h>
#include <math.h>
#include <stdint.h>

#define BATCH 4
#define SEQ   1024
#define DM    1024
#define NH    16
#define HD    64
#define BH    (BATCH*NH)

// Scratch (device globals: allocation-free per harness rules)
__device__ float g_Qh [BATCH*NH*SEQ*HD];        // [B,H,S,hd]  (tf32-rounded)
__device__ float g_Kh [BATCH*NH*SEQ*HD];        // [B,H,S,hd]  (tf32-rounded)
__device__ float g_VhT[BATCH*NH*HD*SEQ];        // [B,H,hd,S]  (tf32-rounded)
__device__ float g_AO [BATCH*SEQ*DM];           // [B,S,D] attn out (fp32)
__device__ float g_PE [SEQ*HD];                 // sinusoidal PE table

// ---------------------------------------------------------------------------
__global__ void pe_init_kernel() {
    int idx = blockIdx.x * blockDim.x + threadIdx.x;
    if (idx >= SEQ * HD) return;
    int s = idx >> 6;
    int d = idx & 63;
    int de = d & ~1;
    float div = expf(-(float)de * 0.14391156831212787f);   // ln(10000)/64
    float ang = (float)s * div;
    g_PE[idx] = (d & 1) ? cosf(ang) : sinf(ang);
}

// ---------------------------------------------------------------------------
__device__ __forceinline__ uint32_t f2tf32(float x) {
    uint32_t r;
    asm("cvt.rna.tf32.f32 %0, %1;" : "=r"(r) : "f"(x));
    return r;
}
__device__ __forceinline__ float tfr(float x) { return __uint_as_float(f2tf32(x)); }

__device__ __forceinline__ void mma8(float* c, const uint32_t* a, const uint32_t* b) {
    asm volatile(
        "mma.sync.aligned.m16n8k8.row.col.f32.tf32.tf32.f32 "
        "{%0,%1,%2,%3},{%4,%5,%6,%7},{%8,%9},{%0,%1,%2,%3};"
        : "+f"(c[0]), "+f"(c[1]), "+f"(c[2]), "+f"(c[3])
        : "r"(a[0]), "r"(a[1]), "r"(a[2]), "r"(a[3]), "r"(b[0]), "r"(b[1]));
}

// Swizzled smem (16-float rows): conflict-free STS.128 + conflict-free scalar LDS
__device__ __forceinline__ void stage16(float* s, int r, int c4, float4 v) {
    float4 w = make_float4(tfr(v.x), tfr(v.y), tfr(v.z), tfr(v.w));
    *(float4*)(s + r * 16 + ((c4 ^ ((r >> 1) & 3)) << 2)) = w;
}
__device__ __forceinline__ uint32_t lds16(const float* s, int r, int c) {
    return __float_as_uint(s[r * 16 + (((c >> 2) ^ ((r >> 1) & 3)) << 2) + (c & 3)]);
}

// ---------------------------------------------------------------------------
// Epilogue dispatch
// ---------------------------------------------------------------------------
template<int EPI>
__device__ __forceinline__ void store_elem(int m, int n, float v,
                                           float* __restrict__ Cex,
                                           const float* __restrict__ bias) {
    if constexpr (EPI == 0 || EPI == 1) {
        int b = m >> 10, s = m & 1023, h = n >> 6, d = n & 63;
        v = tfr(v + bias[n] + g_PE[(s << 6) + d]);
        float* dst = (EPI == 0) ? g_Qh : g_Kh;
        dst[((size_t)((b * NH + h) * SEQ + s)) * HD + d] = v;
    } else if constexpr (EPI == 2) {
        int b = m >> 10, s = m & 1023, h = n >> 6, d = n & 63;
        v = tfr(v + bias[n]);
        g_VhT[((size_t)((b * NH + h) * HD + d)) * SEQ + s] = v;
    } else {
        v += bias[n];
        Cex[(size_t)m * DM + n] = v;
    }
}

// ---------------------------------------------------------------------------
// NT GEMM: C[M,N] = A[M,K] @ B[N,K]^T, K=1024, tf32 mma, fp32 accum.
// CTA 128x128, KC=16, 256 thr, 8 warps as 4(m)x2(n), warp tile 32x64.
// ---------------------------------------------------------------------------
#define KC 16

template<int EPI>
__global__ __launch_bounds__(256, 2)
void gemm_kernel(const float* __restrict__ Aex, const float* __restrict__ Bex,
                 float* __restrict__ Cex, const float* __restrict__ bias) {
    constexpr int K  = 1024;
    constexpr int KT = K / KC;

    const float* A = (EPI == 5) ? g_AO : Aex;
    const float* B = Bex;

    __shared__ float As[2][128 * 16];
    __shared__ float Bs[2][128 * 16];

    const int tid = threadIdx.x;
    const int cm = blockIdx.x * 128;
    const int cn = blockIdx.y * 128;

    const int arow = tid >> 2;          // 0..63
    const int ac4  = tid & 3;           // float4 chunk 0..3
    const float* Aptr0 = A + (size_t)(cm + arow)      * K + ac4 * 4;
    const float* Aptr1 = A + (size_t)(cm + arow + 64) * K + ac4 * 4;
    const float* Bptr0 = B + (size_t)(cn + arow)      * K + ac4 * 4;
    const float* Bptr1 = B + (size_t)(cn + arow + 64) * K + ac4 * 4;

    const int wid  = tid >> 5;
    const int lane = tid & 31;
    const int gid  = lane >> 2;
    const int tg   = lane & 3;
    const int wm = (wid & 3) * 32;
    const int wn = (wid >> 2) * 64;

    float acc[2][8][4];
#pragma unroll
    for (int i = 0; i < 2; i++)
#pragma unroll
        for (int j = 0; j < 8; j++)
#pragma unroll
            for (int l = 0; l < 4; l++) acc[i][j][l] = 0.f;

    // Prologue: stage tile 0
    stage16(As[0], arow,      ac4, *(const float4*)Aptr0);
    stage16(As[0], arow + 64, ac4, *(const float4*)Aptr1);
    stage16(Bs[0], arow,      ac4, *(const float4*)Bptr0);
    stage16(Bs[0], arow + 64, ac4, *(const float4*)Bptr1);
    __syncthreads();

    for (int kt = 0; kt < KT; kt++) {
        const int buf = kt & 1;
        float4 ra0, ra1, rb0, rb1;
        const bool pf = (kt + 1 < KT);
        if (pf) {
            ra0 = *(const float4*)(Aptr0 + (kt + 1) * KC);
            ra1 = *(const float4*)(Aptr1 + (kt + 1) * KC);
            rb0 = *(const float4*)(Bptr0 + (kt + 1) * KC);
            rb1 = *(const float4*)(Bptr1 + (kt + 1) * KC);
        }

        const float* as_ = As[buf];
        const float* bs_ = Bs[buf];
#pragma unroll
        for (int kk = 0; kk < 2; kk++) {
            const int k0 = kk * 8;
            uint32_t af[2][4], bf[8][2];
#pragma unroll
            for (int im = 0; im < 2; im++) {
                int m = wm + im * 16 + gid;
                af[im][0] = lds16(as_, m,     k0 + tg);
                af[im][1] = lds16(as_, m + 8, k0 + tg);
                af[im][2] = lds16(as_, m,     k0 + tg + 4);
                af[im][3] = lds16(as_, m + 8, k0 + tg + 4);
            }
#pragma unroll
            for (int in_ = 0; in_ < 8; in_++) {
                int n = wn + in_ * 8 + gid;
                bf[in_][0] = lds16(bs_, n, k0 + tg);
                bf[in_][1] = lds16(bs_, n, k0 + tg + 4);
            }
#pragma unroll
            for (int im = 0; im < 2; im++)
#pragma unroll
                for (int in_ = 0; in_ < 8; in_++)
                    mma8(acc[im][in_], af[im], bf[in_]);
        }

        if (pf) {
            float* asn = As[buf ^ 1];
            float* bsn = Bs[buf ^ 1];
            stage16(asn, arow,      ac4, ra0);
            stage16(asn, arow + 64, ac4, ra1);
            stage16(bsn, arow,      ac4, rb0);
            stage16(bsn, arow + 64, ac4, rb1);
        }
        __syncthreads();
    }

    // Epilogue
#pragma unroll
    for (int im = 0; im < 2; im++) {
#pragma unroll
        for (int in_ = 0; in_ < 8; in_++) {
            int r0 = cm + wm + im * 16 + gid;
            int c0 = cn + wn + in_ * 8 + tg * 2;
            store_elem<EPI>(r0,     c0,     acc[im][in_][0], Cex, bias);
            store_elem<EPI>(r0,     c0 + 1, acc[im][in_][1], Cex, bias);
            store_elem<EPI>(r0 + 8, c0,     acc[im][in_][2], Cex, bias);
            store_elem<EPI>(r0 + 8, c0 + 1, acc[im][in_][3], Cex, bias);
        }
    }
}

// ---------------------------------------------------------------------------
// Flash attention. Block = (128 q-rows, bh). 256 thr, warp owns 16 q-rows.
// K/V tiles 64x64 in swizzled stride-80 smem. P per warp in [16][84] smem.
// smem floats: Ks 2x5120 | Vs 2x5120 | Ps 8x1344
// ---------------------------------------------------------------------------
#define KVS 80
#define PS  84
#define FLASH_SMEM_FLOATS (20480 + 8 * 16 * PS)
#define FLASH_SMEM_BYTES  (FLASH_SMEM_FLOATS * 4)

__device__ __forceinline__ void stageKV(float* dst, const float4* v, int r, int q) {
    const int sw = (r >> 1) & 3;
#pragma unroll
    for (int i = 0; i < 4; i++) {
        int c4 = q * 4 + i;
        *(float4*)(dst + r * KVS + ((c4 ^ sw) << 2)) = v[i];
    }
}
__device__ __forceinline__ uint32_t ldkv(const float* s, int r, int c) {
    return __float_as_uint(s[r * KVS + (((c >> 2) ^ ((r >> 1) & 3)) << 2) + (c & 3)]);
}

__global__ __launch_bounds__(256, 1)
void flash_kernel() {
    extern __shared__ float sm[];
    float* KsB = sm;                 // 2 x 5120
    float* VsB = sm + 10240;         // 2 x 5120
    float* Ps  = sm + 20480;         // 8 x 16*84

    const int tid  = threadIdx.x;
    const int lane = tid & 31;
    const int w    = tid >> 5;
    const int gid  = lane >> 2;
    const int tg   = lane & 3;
    const int qt   = blockIdx.x;
    const int bh   = blockIdx.y;

    const float* Qb = g_Qh  + (size_t)bh * (SEQ * HD);
    const float* Kb = g_Kh  + (size_t)bh * (SEQ * HD);
    const float* Vb = g_VhT + (size_t)bh * (HD * SEQ);

    // Q fragments (registers, whole hd=64) — values already tf32-rounded
    uint32_t qf[8][4];
    {
        const float* q0 = Qb + (size_t)(qt * 128 + w * 16 + gid) * HD;
        const float* q1 = q0 + 8 * HD;
#pragma unroll
        for (int kk = 0; kk < 8; kk++) {
            qf[kk][0] = __float_as_uint(q0[kk * 8 + tg]);
            qf[kk][1] = __float_as_uint(q1[kk * 8 + tg]);
            qf[kk][2] = __float_as_uint(q0[kk * 8 + tg + 4]);
            qf[kk][3] = __float_as_uint(q1[kk * 8 + tg + 4]);
        }
    }

    // K/V tile loader: thread -> (row ln, chunk group q4)
    const int ln = tid >> 2;          // 0..63
    const int q4 = tid & 3;           // 16-col group
    const int cb = q4 * 16;

    float4 kb[4], vb[4];
#pragma unroll
    for (int i = 0; i < 4; i++) {
        kb[i] = *(const float4*)(Kb + (size_t)ln * HD + cb + i * 4);
        vb[i] = *(const float4*)(Vb + (size_t)ln * SEQ + cb + i * 4);
    }
    stageKV(KsB, kb, ln, q4);
    stageKV(VsB, vb, ln, q4);
    __syncthreads();

    float m0 = -1e30f, m1 = -1e30f, l0 = 0.f, l1 = 0.f;
    float ao[8][4];
#pragma unroll
    for (int t = 0; t < 8; t++)
#pragma unroll
        for (int j = 0; j < 4; j++) ao[t][j] = 0.f;

    float* Pw = Ps + w * (16 * PS);

    for (int kt = 0; kt < 16; kt++) {
        const int buf = kt & 1;
        const float* ks = KsB + buf * 5120;
        const float* vs = VsB + buf * 5120;

        if (kt < 15) {
            const float* Kg = Kb + (size_t)(kt + 1) * 64 * HD;
            const float* Vg = Vb + (kt + 1) * 64;
#pragma unroll
            for (int i = 0; i < 4; i++) {
                kb[i] = *(const float4*)(Kg + (size_t)ln * HD + cb + i * 4);
                vb[i] = *(const float4*)(Vg + (size_t)ln * SEQ + cb + i * 4);
            }
        }

        // S = Q @ K^T  (16 q-rows x 64 keys per warp)
        float s[8][4];
#pragma unroll
        for (int t = 0; t < 8; t++)
#pragma unroll
            for (int j = 0; j < 4; j++) s[t][j] = 0.f;

#pragma unroll
        for (int kk = 0; kk < 8; kk++) {
            const int k0 = kk * 8;
#pragma unroll
            for (int tn = 0; tn < 8; tn++) {
                uint32_t bf[2];
                bf[0] = ldkv(ks, tn * 8 + gid, k0 + tg);
                bf[1] = ldkv(ks, tn * 8 + gid, k0 + tg + 4);
                mma8(s[tn], qf[kk], bf);
            }
        }

        // scale + row max
        float t0 = -1e30f, t1 = -1e30f;
#pragma unroll
        for (int tn = 0; tn < 8; tn++) {
            s[tn][0] *= 0.125f; s[tn][1] *= 0.125f;
            s[tn][2] *= 0.125f; s[tn][3] *= 0.125f;
            t0 = fmaxf(t0, fmaxf(s[tn][0], s[tn][1]));
            t1 = fmaxf(t1, fmaxf(s[tn][2], s[tn][3]));
        }
        t0 = fmaxf(t0, __shfl_xor_sync(0xffffffffu, t0, 1));
        t0 = fmaxf(t0, __shfl_xor_sync(0xffffffffu, t0, 2));
        t1 = fmaxf(t1, __shfl_xor_sync(0xffffffffu, t1, 1));
        t1 = fmaxf(t1, __shfl_xor_sync(0xffffffffu, t1, 2));

        float mn0 = fmaxf(m0, t0), mn1 = fmaxf(m1, t1);
        float a0 = __expf(m0 - mn0), a1 = __expf(m1 - mn1);

        __syncwarp();   // prior P reads done before overwrite
        float rs0 = 0.f, rs1 = 0.f;
#pragma unroll
        for (int tn = 0; tn < 8; tn++) {
            float p0 = __expf(s[tn][0] - mn0);
            float p1 = __expf(s[tn][1] - mn0);
            float p2 = __expf(s[tn][2] - mn1);
            float p3 = __expf(s[tn][3] - mn1);
            rs0 += p0 + p1;
            rs1 += p2 + p3;
            *(float2*)(Pw + gid * PS + tn * 8 + tg * 2)       = make_float2(tfr(p0), tfr(p1));
            *(float2*)(Pw + (gid + 8) * PS + tn * 8 + tg * 2) = make_float2(tfr(p2), tfr(p3));
        }
        rs0 += __shfl_xor_sync(0xffffffffu, rs0, 1);
        rs0 += __shfl_xor_sync(0xffffffffu, rs0, 2);
        rs1 += __shfl_xor_sync(0xffffffffu, rs1, 1);
        rs1 += __shfl_xor_sync(0xffffffffu, rs1, 2);

        l0 = l0 * a0 + rs0;
        l1 = l1 * a1 + rs1;
        m0 = mn0; m1 = mn1;
#pragma unroll
        for (int tn = 0; tn < 8; tn++) {
            ao[tn][0] *= a0; ao[tn][1] *= a0;
            ao[tn][2] *= a1; ao[tn][3] *= a1;
        }
        __syncwarp();   // P visible to all lanes of this warp

        // O += P @ V
#pragma unroll
        for (int kc = 0; kc < 8; kc++) {
            uint32_t pa[4];
            pa[0] = __float_as_uint(Pw[gid * PS + kc * 8 + tg]);
            pa[1] = __float_as_uint(Pw[(gid + 8) * PS + kc * 8 + tg]);
            pa[2] = __float_as_uint(Pw[gid * PS + kc * 8 + tg + 4]);
            pa[3] = __float_as_uint(Pw[(gid + 8) * PS + kc * 8 + tg + 4]);
#pragma unroll
            for (int tn = 0; tn < 8; tn++) {
                uint32_t bf[2];
                bf[0] = ldkv(vs, tn * 8 + gid, kc * 8 + tg);
                bf[1] = ldkv(vs, tn * 8 + gid, kc * 8 + tg + 4);
                mma8(ao[tn], pa, bf);
            }
        }

        if (kt < 15) {
            stageKV(KsB + (buf ^ 1) * 5120, kb, ln, q4);
            stageKV(VsB + (buf ^ 1) * 5120, vb, ln, q4);
        }
        __syncthreads();
    }

    // normalize + store to g_AO [B,S,D]
    float i0 = 1.f / l0, i1 = 1.f / l1;
    int b = bh >> 4, h = bh & 15;
    size_t srow = (size_t)qt * 128 + w * 16 + gid;
    float* O0 = g_AO + ((size_t)b * SEQ + srow) * DM + h * HD + tg * 2;
    float* O1 = O0 + (size_t)8 * DM;
#pragma unroll
    for (int tn = 0; tn < 8; tn++) {
        *(float2*)(O0 + tn * 8) = make_float2(ao[tn][0] * i0, ao[tn][1] * i0);
        *(float2*)(O1 + tn * 8) = make_float2(ao[tn][2] * i1, ao[tn][3] * i1);
    }
}

// ---------------------------------------------------------------------------
extern "C" void kernel_launch(void* const* d_in, const int* in_sizes, int n_in,
                              void* d_out, int out_size) {
    const float* q  = (const float*)d_in[0];
    const float* k  = (const float*)d_in[1];
    const float* v  = (const float*)d_in[2];
    const float* Wq = (const float*)d_in[3];
    const float* bq = (const float*)d_in[4];
    const float* Wk = (const float*)d_in[5];
    const float* bk = (const float*)d_in[6];
    const float* Wv = (const float*)d_in[7];
    const float* bv = (const float*)d_in[8];
    const float* Wo = (const float*)d_in[9];
    const float* bo = (const float*)d_in[10];
    float* out = (float*)d_out;

    cudaFuncSetAttribute(flash_kernel, cudaFuncAttributeMaxDynamicSharedMemorySize,
                         FLASH_SMEM_BYTES);

    pe_init_kernel<<<256, 256>>>();

    gemm_kernel<0><<<dim3(32, 8), 256>>>(q, Wq, nullptr, bq);
    gemm_kernel<1><<<dim3(32, 8), 256>>>(k, Wk, nullptr, bk);
    gemm_kernel<2><<<dim3(32, 8), 256>>>(v, Wv, nullptr, bv);
    flash_kernel<<<dim3(8, 64), 256, FLASH_SMEM_BYTES>>>();
    gemm_kernel<5><<<dim3(32, 8), 256>>>(nullptr, Wo, out, bo);
}